// round 3
// baseline (speedup 1.0000x reference)
#include <cuda_runtime.h>

#define KC     100
#define DD     64
#define CAPC   32768            // per-cluster index-list capacity (mean 20000, +90 sigma)
#define SLICES 47               // warp-tasks per cluster
#define NTASK  (KC * SLICES)    // 4700
#define ABLK   256              // k_accum block = 8 warps
#define AGRID  ((NTASK + 7) / 8) // 588 blocks ~= 4 CTA/SM

// Static scratch (no allocations).
__device__ float    g_sum[KC * DD];     // raw segment sums S_k
__device__ float    g_sumsq[KC];        // Q_k = sum ||x||^2
__device__ int      g_pos[KC];          // per-cluster counts / list cursors
__device__ unsigned g_list[KC * CAPC];  // per-cluster point-index lists (13 MB)
__device__ int      g_is64;             // label dtype: 1 = int64, 0 = int32

// ---------------------------------------------------------------------------
// Kernel 0: zero accumulators + detect label element width.
// int64 labels with values 0..99 have every odd int32 word == 0.
// ---------------------------------------------------------------------------
__global__ void k_init(const void* __restrict__ cl, int n) {
    __shared__ int s_nz;
    if (threadIdx.x == 0) s_nz = 0;
    __syncthreads();

    for (int i = threadIdx.x; i < KC * DD; i += blockDim.x) g_sum[i] = 0.0f;
    if (threadIdx.x < KC) { g_sumsq[threadIdx.x] = 0.0f; g_pos[threadIdx.x] = 0; }

    const int* ci = (const int*)cl;
    int lim = min(1024, n / 2), bad = 0;
    for (int i = threadIdx.x; i < lim; i += blockDim.x)
        if (ci[2 * i + 1] != 0) bad = 1;
    if (bad) atomicOr(&s_nz, 1);
    __syncthreads();
    if (threadIdx.x == 0) g_is64 = (s_nz == 0) ? 1 : 0;
}

// ---------------------------------------------------------------------------
// Kernel 1: bin point indices by cluster. Labels-only pass (8-16 MB).
// ---------------------------------------------------------------------------
__global__ __launch_bounds__(512) void k_bin(const void* __restrict__ cl, int n) {
    const int is64 = g_is64;
    const long long* cl64 = (const long long*)cl;
    const int*       cl32 = (const int*)cl;
    long long tid    = (long long)blockIdx.x * blockDim.x + threadIdx.x;
    long long stride = (long long)gridDim.x * blockDim.x;
    for (long long i = tid; i < n; i += stride) {
        int c = is64 ? (int)__ldg(cl64 + i) : __ldg(cl32 + i);
        int pos = atomicAdd(&g_pos[c], 1);
        if (pos < CAPC) g_list[(size_t)c * CAPC + pos] = (unsigned)i;
    }
}

// ---------------------------------------------------------------------------
// Kernel 2: per-(cluster, slice) warp tasks. One cluster per warp -> fully
// unpredicated register accumulation. Pair-packed LDG.128: lanes 0-15 read
// point i0, lanes 16-31 read i1 (256 B/row, one float4 per lane).
// ---------------------------------------------------------------------------
__global__ __launch_bounds__(ABLK) void k_accum(const float* __restrict__ data) {
    const int lane = threadIdx.x & 31;
    const int task = (blockIdx.x << 3) + (threadIdx.x >> 5);
    if (task >= NTASK) return;

    const int c   = task / SLICES;
    const int s   = task % SLICES;
    const int cnt = min(g_pos[c], CAPC);
    const int per = (cnt + SLICES - 1) / SLICES;
    const int lo  = s * per;
    const int hi  = min(lo + per, cnt);

    const unsigned* __restrict__ list = g_list + (size_t)c * CAPC;
    const float4*   __restrict__ d4   = (const float4*)data;
    const int sub = lane & 15;                 // float4 slot within a row
    const unsigned FULL = 0xffffffffu;

    float ax = 0.f, ay = 0.f, az = 0.f, aw = 0.f, q = 0.f;

    int i = lo;
    for (; i + 32 <= hi; i += 32) {
        unsigned ew = __ldg(list + i + lane);   // 32 indices, coalesced
#pragma unroll
        for (int g = 0; g < 2; g++) {
            unsigned idx[8];
#pragma unroll
            for (int p = 0; p < 8; p++) {
                unsigned i0 = __shfl_sync(FULL, ew, g * 16 + 2 * p);
                unsigned i1 = __shfl_sync(FULL, ew, g * 16 + 2 * p + 1);
                idx[p] = (lane < 16) ? i0 : i1;
            }
            float4 v[8];
#pragma unroll
            for (int p = 0; p < 8; p++)         // 8 LDG.128 in flight
                v[p] = __ldcs(d4 + ((size_t)idx[p] * 16 + sub));
#pragma unroll
            for (int p = 0; p < 8; p++) {
                ax += v[p].x; ay += v[p].y; az += v[p].z; aw += v[p].w;
                q = fmaf(v[p].x, v[p].x, q); q = fmaf(v[p].y, v[p].y, q);
                q = fmaf(v[p].z, v[p].z, q); q = fmaf(v[p].w, v[p].w, q);
            }
        }
    }
    int rem = hi - i;
    if (rem > 0) {
        unsigned ew = __ldg(list + i + min(lane, rem - 1));
        int npair = rem >> 1;
        for (int p = 0; p < npair; p++) {
            unsigned i0 = __shfl_sync(FULL, ew, 2 * p);
            unsigned i1 = __shfl_sync(FULL, ew, 2 * p + 1);
            unsigned idx = (lane < 16) ? i0 : i1;
            float4 v = __ldcs(d4 + ((size_t)idx * 16 + sub));
            ax += v.x; ay += v.y; az += v.z; aw += v.w;
            q = fmaf(v.x, v.x, q); q = fmaf(v.y, v.y, q);
            q = fmaf(v.z, v.z, q); q = fmaf(v.w, v.w, q);
        }
        if (rem & 1) {
            unsigned i0 = __shfl_sync(FULL, ew, rem - 1);
            if (lane < 16) {
                float4 v = __ldcs(d4 + ((size_t)i0 * 16 + sub));
                ax += v.x; ay += v.y; az += v.z; aw += v.w;
                q = fmaf(v.x, v.x, q); q = fmaf(v.y, v.y, q);
                q = fmaf(v.z, v.z, q); q = fmaf(v.w, v.w, q);
            }
        }
    }

    // combine the two half-warps (same dims), then flush
    ax += __shfl_xor_sync(FULL, ax, 16);
    ay += __shfl_xor_sync(FULL, ay, 16);
    az += __shfl_xor_sync(FULL, az, 16);
    aw += __shfl_xor_sync(FULL, aw, 16);
#pragma unroll
    for (int o = 16; o; o >>= 1) q += __shfl_xor_sync(FULL, q, o);

    if (lane < 16) {
        float* dst = g_sum + c * DD + lane * 4;
        atomicAdd(dst + 0, ax);
        atomicAdd(dst + 1, ay);
        atomicAdd(dst + 2, az);
        atomicAdd(dst + 3, aw);
    }
    if (lane == 0) atomicAdd(&g_sumsq[c], q);
}

// ---------------------------------------------------------------------------
// Kernel 3: fused epilogue, single block. A_k, Si_k via Q - 2A.S + n||A||^2,
// row-wise max of Rij, final mean -> scalar.
// ---------------------------------------------------------------------------
__global__ __launch_bounds__(1024) void k_epi(float* __restrict__ out) {
    __shared__ float s_A[KC * (DD + 1)];  // padded: conflict-free j-reads
    __shared__ float s_Si[KC];
    __shared__ float s_rm[KC];
    const int tid = threadIdx.x;

    for (int idx = tid; idx < KC * DD; idx += 1024) {
        int k = idx >> 6, d = idx & 63;
        s_A[k * 65 + d] = (g_sum[idx] + 0.001f) / ((float)g_pos[k] + 1.0f);
    }
    __syncthreads();

    for (int k = tid; k < KC; k += 1024) {
        float nk = (float)g_pos[k], dot = 0.0f, a2 = 0.0f;
#pragma unroll 8
        for (int d = 0; d < DD; d++) {
            float av = s_A[k * 65 + d], sv = g_sum[k * DD + d];
            dot = fmaf(av, sv, dot);
            a2  = fmaf(av, av, a2);
        }
        float ss = g_sumsq[k] - 2.0f * dot + nk * a2;
        s_Si[k] = sqrtf((0.001f + ss) / (nk + 1.0f));
    }
    __syncthreads();

    const int w = tid >> 5, lane = tid & 31;
    for (int r = w; r < KC; r += 32) {
        float si = s_Si[r], m = 0.0f;
        for (int j = lane; j < KC; j += 32) {
            if (j == r) continue;
            float d2 = 0.0f;
#pragma unroll 8
            for (int d = 0; d < DD; d++) {
                float df = s_A[r * 65 + d] - s_A[j * 65 + d];
                d2 = fmaf(df, df, d2);
            }
            m = fmaxf(m, (si + s_Si[j]) / sqrtf(d2));
        }
#pragma unroll
        for (int o = 16; o; o >>= 1) m = fmaxf(m, __shfl_xor_sync(0xffffffffu, m, o));
        if (lane == 0) s_rm[r] = m;
    }
    __syncthreads();
    if (tid == 0) {
        float tsum = 0.0f;
        for (int k = 0; k < KC; k++) tsum += s_rm[k];
        out[0] = tsum / (float)KC;
    }
}

// ---------------------------------------------------------------------------
extern "C" void kernel_launch(void* const* d_in, const int* in_sizes, int n_in,
                              void* d_out, int out_size) {
    const float* data;
    const void*  cl;
    int          n;
    if (in_sizes[0] >= in_sizes[1]) {
        data = (const float*)d_in[0]; cl = d_in[1]; n = in_sizes[1];
    } else {
        data = (const float*)d_in[1]; cl = d_in[0]; n = in_sizes[0];
    }

    k_init <<<1, 1024>>>(cl, n);
    k_bin  <<<1184, 512>>>(cl, n);
    k_accum<<<AGRID, ABLK>>>(data);
    k_epi  <<<1, 1024>>>((float*)d_out);
}

// round 4
// speedup vs baseline: 3.1400x; 3.1400x over previous
#include <cuda_runtime.h>

#define KC   100
#define DD   64
#define TP   1024
#define CAP  48              // per-cluster per-tile list capacity (mean 10.2, ~11 sigma)
#define WPB  25              // warp w owns clusters [4w, 4w+4)
#define TPB  800

// Static scratch (no allocations).
__device__ float g_sum[KC * DD];
__device__ float g_sumsq[KC];
__device__ int   g_cnti[KC];
__device__ float g_rowmax[KC];
__device__ int   g_is64;

// ---------------------------------------------------------------------------
// Kernel 0: zero accumulators + detect label width (int64 labels 0..99 have
// every odd int32 word == 0).
// ---------------------------------------------------------------------------
__global__ void k_init(const void* __restrict__ cl, int n) {
    __shared__ int s_nz;
    if (threadIdx.x == 0) s_nz = 0;
    __syncthreads();

    for (int i = threadIdx.x; i < KC * DD; i += blockDim.x) g_sum[i] = 0.0f;
    if (threadIdx.x < KC) { g_sumsq[threadIdx.x] = 0.0f; g_cnti[threadIdx.x] = 0; }

    const int* ci = (const int*)cl;
    int lim = min(1024, n / 2), bad = 0;
    for (int i = threadIdx.x; i < lim; i += blockDim.x)
        if (ci[2 * i + 1] != 0) bad = 1;
    if (bad) atomicOr(&s_nz, 1);
    __syncthreads();
    if (threadIdx.x == 0) g_is64 = (s_nz == 0) ? 1 : 0;
}

// ---------------------------------------------------------------------------
// Kernel 1: streaming accumulation. Per tile: block-cooperative binning into
// per-cluster smem lists (labels read ONCE), double-buffered so bin(t+1)
// overlaps accumulate(t). Warp owns 4 clusters -> unpredicated register
// accumulate with pair-packed LDG.128.
// ---------------------------------------------------------------------------
__global__ __launch_bounds__(TPB, 1) void k_accum(const float* __restrict__ data,
                                                  const void* __restrict__ cl,
                                                  int n) {
    __shared__ short s_list[2][KC][CAP];   // 19.2 KB
    __shared__ int   s_cnt[2][KC];

    const int tid   = threadIdx.x;
    const int lane  = tid & 31;
    const int w     = tid >> 5;
    const int cbase = w << 2;
    const int sub   = lane & 15;    // float4 slot within a 64-float row
    const int half  = lane >> 4;    // 0: even list entries, 1: odd
    const int is64  = g_is64;
    const unsigned FULL = 0xffffffffu;

    const long long* cl64 = (const long long*)cl;
    const int*       cl32 = (const int*)cl;
    const float4*    d4   = (const float4*)data;

    float4 a0 = {0,0,0,0}, a1 = {0,0,0,0}, a2 = {0,0,0,0}, a3 = {0,0,0,0};
    float  q0 = 0, q1 = 0, q2 = 0, q3 = 0;
    int    n0 = 0, n1 = 0, n2 = 0, n3 = 0;

    const int ntiles = (n + TP - 1) / TP;

    // ---- bin tile t into buffer b (whole block cooperates; labels once) ----
    auto bin = [&](int t, int b) {
        long long tb = (long long)t * TP;
        int tn = min(TP, (int)((long long)n - tb));
        for (int i = tid; i < tn; i += TPB) {
            int c = is64 ? (int)__ldg(cl64 + tb + i) : __ldg(cl32 + tb + i);
            int pos = atomicAdd(&s_cnt[b][c], 1);
            if (pos < CAP) {
                s_list[b][c][pos] = (short)i;
            } else {                       // astronomically rare: direct path
                const float4* r = d4 + (tb + i) * 16;
                float qq = 0.0f;
                for (int u = 0; u < 16; u++) {
                    float4 v = __ldg(r + u);
                    atomicAdd(&g_sum[c * DD + u * 4 + 0], v.x);
                    atomicAdd(&g_sum[c * DD + u * 4 + 1], v.y);
                    atomicAdd(&g_sum[c * DD + u * 4 + 2], v.z);
                    atomicAdd(&g_sum[c * DD + u * 4 + 3], v.w);
                    qq = fmaf(v.x, v.x, qq); qq = fmaf(v.y, v.y, qq);
                    qq = fmaf(v.z, v.z, qq); qq = fmaf(v.w, v.w, qq);
                }
                atomicAdd(&g_sumsq[c], qq);
                atomicAdd(&g_cnti[c], 1);
            }
        }
    };

    // ---- accumulate tile t from buffer b (warp-private clusters) ----------
#define CLUSTER(J, A, Q, NN)                                                 \
    {                                                                        \
        int len = min(s_cnt[b][cbase + J], CAP);                             \
        const short* lst = s_list[b][cbase + J];                             \
        int i = 0;                                                           \
        for (; i + 8 <= len; i += 8) {                                       \
            int e0 = lst[i + 0 + half];                                      \
            int e1 = lst[i + 2 + half];                                      \
            int e2 = lst[i + 4 + half];                                      \
            int e3 = lst[i + 6 + half];                                      \
            float4 v0 = __ldcs(d4 + (tb + e0) * 16 + sub);                   \
            float4 v1 = __ldcs(d4 + (tb + e1) * 16 + sub);                   \
            float4 v2 = __ldcs(d4 + (tb + e2) * 16 + sub);                   \
            float4 v3 = __ldcs(d4 + (tb + e3) * 16 + sub);                   \
            A.x += v0.x + v1.x; A.x += v2.x + v3.x;                          \
            A.y += v0.y + v1.y; A.y += v2.y + v3.y;                          \
            A.z += v0.z + v1.z; A.z += v2.z + v3.z;                          \
            A.w += v0.w + v1.w; A.w += v2.w + v3.w;                          \
            Q = fmaf(v0.x, v0.x, Q); Q = fmaf(v0.y, v0.y, Q);                \
            Q = fmaf(v0.z, v0.z, Q); Q = fmaf(v0.w, v0.w, Q);                \
            Q = fmaf(v1.x, v1.x, Q); Q = fmaf(v1.y, v1.y, Q);                \
            Q = fmaf(v1.z, v1.z, Q); Q = fmaf(v1.w, v1.w, Q);                \
            Q = fmaf(v2.x, v2.x, Q); Q = fmaf(v2.y, v2.y, Q);                \
            Q = fmaf(v2.z, v2.z, Q); Q = fmaf(v2.w, v2.w, Q);                \
            Q = fmaf(v3.x, v3.x, Q); Q = fmaf(v3.y, v3.y, Q);                \
            Q = fmaf(v3.z, v3.z, Q); Q = fmaf(v3.w, v3.w, Q);                \
        }                                                                    \
        for (; i + 2 <= len; i += 2) {                                       \
            int e = lst[i + half];                                           \
            float4 v = __ldcs(d4 + (tb + e) * 16 + sub);                     \
            A.x += v.x; A.y += v.y; A.z += v.z; A.w += v.w;                  \
            Q = fmaf(v.x, v.x, Q); Q = fmaf(v.y, v.y, Q);                    \
            Q = fmaf(v.z, v.z, Q); Q = fmaf(v.w, v.w, Q);                    \
        }                                                                    \
        if (i < len && half == 0) {                                          \
            int e = lst[i];                                                  \
            float4 v = __ldcs(d4 + (tb + e) * 16 + sub);                     \
            A.x += v.x; A.y += v.y; A.z += v.z; A.w += v.w;                  \
            Q = fmaf(v.x, v.x, Q); Q = fmaf(v.y, v.y, Q);                    \
            Q = fmaf(v.z, v.z, Q); Q = fmaf(v.w, v.w, Q);                    \
        }                                                                    \
        NN += len;                                                           \
    }

    // ---- prologue: bin first tile --------------------------------------
    int t0 = blockIdx.x;
    if (t0 < ntiles) {
        for (int c = tid; c < KC; c += TPB) s_cnt[0][c] = 0;
        __syncthreads();
        bin(t0, 0);
    }

    int buf = 0;
    for (int t = t0; t < ntiles; t += gridDim.x) {
        long long tb = (long long)t * TP;
        int tnext = t + gridDim.x;
        __syncthreads();                        // bin(t) + phaseB(t-g) done
        if (tnext < ntiles) {
            for (int c = tid; c < KC; c += TPB) s_cnt[buf ^ 1][c] = 0;
        }
        __syncthreads();
        if (tnext < ntiles) bin(tnext, buf ^ 1);   // overlaps phaseB(t)

        const int b = buf;
        CLUSTER(0, a0, q0, n0)
        CLUSTER(1, a1, q1, n1)
        CLUSTER(2, a2, q2, n2)
        CLUSTER(3, a3, q3, n3)
        buf ^= 1;
    }
#undef CLUSTER

    // ---- flush ----------------------------------------------------------
#define FLUSH(J, A, Q, NN)                                                   \
    {                                                                        \
        A.x += __shfl_xor_sync(FULL, A.x, 16);                               \
        A.y += __shfl_xor_sync(FULL, A.y, 16);                               \
        A.z += __shfl_xor_sync(FULL, A.z, 16);                               \
        A.w += __shfl_xor_sync(FULL, A.w, 16);                               \
        float qq = Q;                                                        \
        for (int o = 16; o; o >>= 1) qq += __shfl_xor_sync(FULL, qq, o);     \
        if (lane < 16) {                                                     \
            float* dst = g_sum + (cbase + J) * DD + sub * 4;                 \
            atomicAdd(dst + 0, A.x);                                         \
            atomicAdd(dst + 1, A.y);                                         \
            atomicAdd(dst + 2, A.z);                                         \
            atomicAdd(dst + 3, A.w);                                         \
        }                                                                    \
        if (lane == 0) {                                                     \
            atomicAdd(&g_sumsq[cbase + J], qq);                              \
            atomicAdd(&g_cnti[cbase + J], NN);                               \
        }                                                                    \
    }
    FLUSH(0, a0, q0, n0)
    FLUSH(1, a1, q1, n1)
    FLUSH(2, a2, q2, n2)
    FLUSH(3, a3, q3, n3)
#undef FLUSH
}

// ---------------------------------------------------------------------------
// Kernel 2: one block per cluster-row i: A, Si (tiny recompute), row max.
// ---------------------------------------------------------------------------
__global__ __launch_bounds__(128) void k_rows() {
    __shared__ float s_A[KC * (DD + 1)];   // padded: conflict-free j-reads
    __shared__ float s_Si[KC];
    __shared__ float s_red[4];

    for (int idx = threadIdx.x; idx < KC * DD; idx += 128) {
        int k = idx >> 6, d = idx & 63;
        s_A[k * 65 + d] = (g_sum[idx] + 0.001f) / ((float)g_cnti[k] + 1.0f);
    }
    __syncthreads();

    for (int k = threadIdx.x; k < KC; k += 128) {
        float nk = (float)g_cnti[k], dot = 0.0f, a2 = 0.0f;
#pragma unroll 8
        for (int d = 0; d < DD; d++) {
            float av = s_A[k * 65 + d], sv = g_sum[k * DD + d];
            dot = fmaf(av, sv, dot);
            a2  = fmaf(av, av, a2);
        }
        float ss = g_sumsq[k] - 2.0f * dot + nk * a2;
        s_Si[k] = sqrtf((0.001f + ss) / (nk + 1.0f));
    }
    __syncthreads();

    const int i = blockIdx.x;
    const float si = s_Si[i];
    float m = 0.0f;
    for (int j = threadIdx.x; j < KC; j += 128) {
        if (j == i) continue;
        float d2 = 0.0f;
#pragma unroll 8
        for (int d = 0; d < DD; d++) {
            float df = s_A[i * 65 + d] - s_A[j * 65 + d];
            d2 = fmaf(df, df, d2);
        }
        m = fmaxf(m, (si + s_Si[j]) / sqrtf(d2));
    }
#pragma unroll
    for (int o = 16; o; o >>= 1) m = fmaxf(m, __shfl_xor_sync(0xffffffffu, m, o));
    if ((threadIdx.x & 31) == 0) s_red[threadIdx.x >> 5] = m;
    __syncthreads();
    if (threadIdx.x == 0)
        g_rowmax[i] = fmaxf(fmaxf(s_red[0], s_red[1]), fmaxf(s_red[2], s_red[3]));
}

// ---------------------------------------------------------------------------
// Kernel 3: final mean -> scalar.
// ---------------------------------------------------------------------------
__global__ void k_final(float* __restrict__ out) {
    if (threadIdx.x == 0) {
        float t = 0.0f;
        for (int k = 0; k < KC; k++) t += g_rowmax[k];
        out[0] = t / (float)KC;
    }
}

// ---------------------------------------------------------------------------
extern "C" void kernel_launch(void* const* d_in, const int* in_sizes, int n_in,
                              void* d_out, int out_size) {
    const float* data;
    const void*  cl;
    int          n;
    if (in_sizes[0] >= in_sizes[1]) {
        data = (const float*)d_in[0]; cl = d_in[1]; n = in_sizes[1];
    } else {
        data = (const float*)d_in[1]; cl = d_in[0]; n = in_sizes[0];
    }

    k_init <<<1, 1024>>>(cl, n);
    k_accum<<<296, TPB>>>(data, cl, n);
    k_rows <<<KC, 128>>>();
    k_final<<<1, 32>>>((float*)d_out);
}

// round 5
// speedup vs baseline: 4.3827x; 1.3958x over previous
#include <cuda_runtime.h>

#define KC   100
#define DD   64
#define CAP  224
#define WPB  25
#define TPB  800
#define NBLK 148

// Static scratch (no allocations).
__device__ float g_sum[KC * DD];
__device__ float g_sumsq[KC];
__device__ int   g_cnti[KC];
__device__ float g_rowmax[KC];
__device__ int   g_done;
__device__ int   g_is64;

// ---------------------------------------------------------------------------
// Kernel 0: zero accumulators + detect label width (int64 labels 0..99 have
// every odd int32 word == 0).
// ---------------------------------------------------------------------------
__global__ void k_init(const void* __restrict__ cl, int n) {
    __shared__ int s_nz;
    if (threadIdx.x == 0) s_nz = 0;
    __syncthreads();

    for (int i = threadIdx.x; i < KC * DD; i += blockDim.x) g_sum[i] = 0.0f;
    if (threadIdx.x < KC) { g_sumsq[threadIdx.x] = 0.0f; g_cnti[threadIdx.x] = 0; }
    if (threadIdx.x == 0) g_done = 0;

    const int* ci = (const int*)cl;
    int lim = min(1024, n / 2), bad = 0;
    for (int i = threadIdx.x; i < lim; i += blockDim.x)
        if (ci[2 * i + 1] != 0) bad = 1;
    if (bad) atomicOr(&s_nz, 1);
    __syncthreads();
    if (threadIdx.x == 0) g_is64 = (s_nz == 0) ? 1 : 0;
}

// ---------------------------------------------------------------------------
// Per-cluster accumulate: pair-packed LDG.128 gathers, batch-8 MLP.
// lanes 0-15 take even list entries, 16-31 odd; each lane one float4 of a row.
// ---------------------------------------------------------------------------
__device__ __forceinline__ void accum_cluster(const float4* __restrict__ d4s,
                                              const unsigned short* __restrict__ lst,
                                              int len, int sub, int half,
                                              float4& A, float& Q) {
    int i = 0;
    for (; i + 16 <= len; i += 16) {
        int e0 = lst[i + 0  + half], e1 = lst[i + 2  + half];
        int e2 = lst[i + 4  + half], e3 = lst[i + 6  + half];
        int e4 = lst[i + 8  + half], e5 = lst[i + 10 + half];
        int e6 = lst[i + 12 + half], e7 = lst[i + 14 + half];
        float4 v0 = __ldcs(d4s + e0 * 16 + sub);
        float4 v1 = __ldcs(d4s + e1 * 16 + sub);
        float4 v2 = __ldcs(d4s + e2 * 16 + sub);
        float4 v3 = __ldcs(d4s + e3 * 16 + sub);
        float4 v4 = __ldcs(d4s + e4 * 16 + sub);
        float4 v5 = __ldcs(d4s + e5 * 16 + sub);
        float4 v6 = __ldcs(d4s + e6 * 16 + sub);
        float4 v7 = __ldcs(d4s + e7 * 16 + sub);
        A.x += v0.x + v1.x + v2.x + v3.x + v4.x + v5.x + v6.x + v7.x;
        A.y += v0.y + v1.y + v2.y + v3.y + v4.y + v5.y + v6.y + v7.y;
        A.z += v0.z + v1.z + v2.z + v3.z + v4.z + v5.z + v6.z + v7.z;
        A.w += v0.w + v1.w + v2.w + v3.w + v4.w + v5.w + v6.w + v7.w;
        Q = fmaf(v0.x, v0.x, Q); Q = fmaf(v0.y, v0.y, Q);
        Q = fmaf(v0.z, v0.z, Q); Q = fmaf(v0.w, v0.w, Q);
        Q = fmaf(v1.x, v1.x, Q); Q = fmaf(v1.y, v1.y, Q);
        Q = fmaf(v1.z, v1.z, Q); Q = fmaf(v1.w, v1.w, Q);
        Q = fmaf(v2.x, v2.x, Q); Q = fmaf(v2.y, v2.y, Q);
        Q = fmaf(v2.z, v2.z, Q); Q = fmaf(v2.w, v2.w, Q);
        Q = fmaf(v3.x, v3.x, Q); Q = fmaf(v3.y, v3.y, Q);
        Q = fmaf(v3.z, v3.z, Q); Q = fmaf(v3.w, v3.w, Q);
        Q = fmaf(v4.x, v4.x, Q); Q = fmaf(v4.y, v4.y, Q);
        Q = fmaf(v4.z, v4.z, Q); Q = fmaf(v4.w, v4.w, Q);
        Q = fmaf(v5.x, v5.x, Q); Q = fmaf(v5.y, v5.y, Q);
        Q = fmaf(v5.z, v5.z, Q); Q = fmaf(v5.w, v5.w, Q);
        Q = fmaf(v6.x, v6.x, Q); Q = fmaf(v6.y, v6.y, Q);
        Q = fmaf(v6.z, v6.z, Q); Q = fmaf(v6.w, v6.w, Q);
        Q = fmaf(v7.x, v7.x, Q); Q = fmaf(v7.y, v7.y, Q);
        Q = fmaf(v7.z, v7.z, Q); Q = fmaf(v7.w, v7.w, Q);
    }
    for (; i + 2 <= len; i += 2) {
        int e = lst[i + half];
        float4 v = __ldcs(d4s + e * 16 + sub);
        A.x += v.x; A.y += v.y; A.z += v.z; A.w += v.w;
        Q = fmaf(v.x, v.x, Q); Q = fmaf(v.y, v.y, Q);
        Q = fmaf(v.z, v.z, Q); Q = fmaf(v.w, v.w, Q);
    }
    if (i < len && half == 0) {
        int e = lst[i];
        float4 v = __ldcs(d4s + e * 16 + sub);
        A.x += v.x; A.y += v.y; A.z += v.z; A.w += v.w;
        Q = fmaf(v.x, v.x, Q); Q = fmaf(v.y, v.y, Q);
        Q = fmaf(v.z, v.z, Q); Q = fmaf(v.w, v.w, Q);
    }
}

// ---------------------------------------------------------------------------
// Kernel 1: one contiguous range per block (equal work by construction).
// Bin once -> measured snake assignment of clusters to warps (balanced) ->
// unpredicated register accumulate -> REDG flush.
// ---------------------------------------------------------------------------
__global__ __launch_bounds__(TPB, 1) void k_accum(const float* __restrict__ data,
                                                  const void* __restrict__ cl,
                                                  int n) {
    __shared__ unsigned short s_list[KC][CAP];   // 44.8 KB
    __shared__ int s_cnt[KC];
    __shared__ int s_asg[WPB][4];
    __shared__ int s_gc[WPB];

    const int tid  = threadIdx.x;
    const int lane = tid & 31;
    const int w    = tid >> 5;
    const int sub  = lane & 15;
    const int half = lane >> 4;
    const int is64 = g_is64;
    const unsigned FULL = 0xffffffffu;

    const int share = (n + NBLK - 1) / NBLK;            // <= 32767 for this N
    const long long start = (long long)blockIdx.x * share;
    if (start >= n) return;                              // uniform per block
    const int bn = (int)min((long long)share, (long long)n - start);

    const long long* cl64 = (const long long*)cl + start;
    const int*       cl32 = (const int*)cl + start;
    const float4*    d4s  = (const float4*)data + start * 16;

    for (int c = tid; c < KC; c += TPB) s_cnt[c] = 0;
    if (tid < WPB) s_gc[tid] = 0;
    __syncthreads();

    // ---- bin (labels read once) ----------------------------------------
    for (int i = tid; i < bn; i += TPB) {
        int c = is64 ? (int)__ldg(cl64 + i) : __ldg(cl32 + i);
        int pos = atomicAdd(&s_cnt[c], 1);
        if (pos < CAP) {
            s_list[c][pos] = (unsigned short)i;
        } else {                                   // astronomically rare
            const float4* r = d4s + i * 16;
            float qq = 0.0f;
            for (int u = 0; u < 16; u++) {
                float4 v = __ldg(r + u);
                atomicAdd(&g_sum[c * DD + u * 4 + 0], v.x);
                atomicAdd(&g_sum[c * DD + u * 4 + 1], v.y);
                atomicAdd(&g_sum[c * DD + u * 4 + 2], v.z);
                atomicAdd(&g_sum[c * DD + u * 4 + 3], v.w);
                qq = fmaf(v.x, v.x, qq); qq = fmaf(v.y, v.y, qq);
                qq = fmaf(v.z, v.z, qq); qq = fmaf(v.w, v.w, qq);
            }
            atomicAdd(&g_sumsq[c], qq);
            atomicAdd(&g_cnti[c], 1);
        }
    }
    __syncthreads();

    // ---- measured assignment: rank clusters by count, snake-deal to warps
    if (tid < KC) {
        int cc = s_cnt[tid];
        int r = 0;
        for (int j = 0; j < KC; j++) {
            int cj = s_cnt[j];
            r += (cj > cc) || (cj == cc && j < tid);
        }
        int q = r / WPB, p = r % WPB;
        int g = (q & 1) ? (WPB - 1 - p) : p;
        int slot = atomicAdd(&s_gc[g], 1);
        s_asg[g][slot] = tid;
        atomicAdd(&g_cnti[tid], min(cc, CAP));
    }
    __syncthreads();

    // ---- accumulate: warp handles its 4 assigned clusters ---------------
    const int c0 = s_asg[w][0], c1 = s_asg[w][1];
    const int c2 = s_asg[w][2], c3 = s_asg[w][3];
    float4 a0 = {0,0,0,0}, a1 = {0,0,0,0}, a2 = {0,0,0,0}, a3 = {0,0,0,0};
    float  q0 = 0, q1 = 0, q2 = 0, q3 = 0;
    accum_cluster(d4s, s_list[c0], min(s_cnt[c0], CAP), sub, half, a0, q0);
    accum_cluster(d4s, s_list[c1], min(s_cnt[c1], CAP), sub, half, a1, q1);
    accum_cluster(d4s, s_list[c2], min(s_cnt[c2], CAP), sub, half, a2, q2);
    accum_cluster(d4s, s_list[c3], min(s_cnt[c3], CAP), sub, half, a3, q3);

    // ---- flush ----------------------------------------------------------
#define FLUSH(C, A, Q)                                                       \
    {                                                                        \
        A.x += __shfl_xor_sync(FULL, A.x, 16);                               \
        A.y += __shfl_xor_sync(FULL, A.y, 16);                               \
        A.z += __shfl_xor_sync(FULL, A.z, 16);                               \
        A.w += __shfl_xor_sync(FULL, A.w, 16);                               \
        float qq = Q;                                                        \
        for (int o = 16; o; o >>= 1) qq += __shfl_xor_sync(FULL, qq, o);     \
        if (lane < 16) {                                                     \
            float* dst = g_sum + (C) * DD + sub * 4;                         \
            atomicAdd(dst + 0, A.x);                                         \
            atomicAdd(dst + 1, A.y);                                         \
            atomicAdd(dst + 2, A.z);                                         \
            atomicAdd(dst + 3, A.w);                                         \
        }                                                                    \
        if (lane == 0) atomicAdd(&g_sumsq[C], qq);                           \
    }
    FLUSH(c0, a0, q0)
    FLUSH(c1, a1, q1)
    FLUSH(c2, a2, q2)
    FLUSH(c3, a3, q3)
#undef FLUSH
}

// ---------------------------------------------------------------------------
// Kernel 2: one block per cluster-row: A, Si, row max; last block finishes.
// ---------------------------------------------------------------------------
__global__ __launch_bounds__(128) void k_rows(float* __restrict__ out) {
    __shared__ float s_A[KC * (DD + 1)];   // padded: conflict-free j-reads
    __shared__ float s_Si[KC];
    __shared__ float s_red[4];

    for (int idx = threadIdx.x; idx < KC * DD; idx += 128) {
        int k = idx >> 6, d = idx & 63;
        s_A[k * 65 + d] = (g_sum[idx] + 0.001f) / ((float)g_cnti[k] + 1.0f);
    }
    __syncthreads();

    for (int k = threadIdx.x; k < KC; k += 128) {
        float nk = (float)g_cnti[k], dot = 0.0f, a2 = 0.0f;
#pragma unroll 8
        for (int d = 0; d < DD; d++) {
            float av = s_A[k * 65 + d], sv = g_sum[k * DD + d];
            dot = fmaf(av, sv, dot);
            a2  = fmaf(av, av, a2);
        }
        float ss = g_sumsq[k] - 2.0f * dot + nk * a2;
        s_Si[k] = sqrtf((0.001f + ss) / (nk + 1.0f));
    }
    __syncthreads();

    const int i = blockIdx.x;
    const float si = s_Si[i];
    float m = 0.0f;
    for (int j = threadIdx.x; j < KC; j += 128) {
        if (j == i) continue;
        float d2 = 0.0f;
#pragma unroll 8
        for (int d = 0; d < DD; d++) {
            float df = s_A[i * 65 + d] - s_A[j * 65 + d];
            d2 = fmaf(df, df, d2);
        }
        m = fmaxf(m, (si + s_Si[j]) / sqrtf(d2));
    }
#pragma unroll
    for (int o = 16; o; o >>= 1) m = fmaxf(m, __shfl_xor_sync(0xffffffffu, m, o));
    if ((threadIdx.x & 31) == 0) s_red[threadIdx.x >> 5] = m;
    __syncthreads();

    if (threadIdx.x == 0) {
        g_rowmax[i] = fmaxf(fmaxf(s_red[0], s_red[1]), fmaxf(s_red[2], s_red[3]));
        __threadfence();
        int t = atomicAdd(&g_done, 1);
        if (t == KC - 1) {                        // last block: finish scalar
            __threadfence();
            volatile float* rm = g_rowmax;
            float tsum = 0.0f;
            for (int k = 0; k < KC; k++) tsum += rm[k];
            out[0] = tsum / (float)KC;
        }
    }
}

// ---------------------------------------------------------------------------
extern "C" void kernel_launch(void* const* d_in, const int* in_sizes, int n_in,
                              void* d_out, int out_size) {
    const float* data;
    const void*  cl;
    int          n;
    if (in_sizes[0] >= in_sizes[1]) {
        data = (const float*)d_in[0]; cl = d_in[1]; n = in_sizes[1];
    } else {
        data = (const float*)d_in[1]; cl = d_in[0]; n = in_sizes[0];
    }

    k_init <<<1, 1024>>>(cl, n);
    k_accum<<<NBLK, TPB>>>(data, cl, n);
    k_rows <<<KC, 128>>>((float*)d_out);
}